// round 13
// baseline (speedup 1.0000x reference)
#include <cuda_runtime.h>
#include <cuda_fp16.h>
#include <mma.h>
#include <cstdint>

using namespace nvcuda;

#define T_TOK 4096
#define DDIM  768
#define IDIM  2048
#define NEXP  8
#define TM    128
#define NTILES 40
#define PADROWS (NTILES*TM)
#define KC    64             // halves per K chunk
#define LDH   72             // padded row length (halves): 144B rows, conflict-free ldmatrix
#define LDST  132            // fp32 staging stride (gemm2): %4==0, row %16B==0
#define LDST2 68             // fp32 staging stride (gemm1, 64 cols)
#define TILE_BYTES (128 * LDH * 2)       // 18432 B contiguous A or B chunk
#define STAGE_BYTES (2 * TILE_BYTES)     // 36864
#define NSTAGE 2
#define GSMEM (NSTAGE * STAGE_BYTES)     // 73728 -> 3 CTA/SM

// ---------------- device-global scratch (tiled layouts, no allocation) ------
__device__ int    g_perm[PADROWS];
__device__ int    g_tile_expert[NTILES];
__device__ int    g_flag[NTILES * 6];    // gemm2 z=0 -> z=1 handshake
// [e][y:32][kc:12][r:128][72]  rows interleaved [G0-31|U0-31|G32-63|U32-63]
__device__ __half g_wgu[(size_t)NEXP * 32 * 12 * 128 * LDH];
// [e][y:6][kc:32][r:128][72]
__device__ __half g_wdt[(size_t)NEXP * 6 * 32 * 128 * LDH];
// [tile:40][kc:12][r:128][72]
__device__ __half g_xt [(size_t)NTILES * 12 * 128 * LDH];
// [tile:40][kc:32][r:128][72]
__device__ __half g_ht [(size_t)NTILES * 32 * 128 * LDH];
// split-K z=0 partials, permuted row order: [PADROWS][768]
__device__ float  g_gp [(size_t)PADROWS * DDIM];

// ---------------- PTX helpers -----------------------------------------------
__device__ __forceinline__ uint32_t smem_u32(const void* p) {
    uint32_t a;
    asm("{ .reg .u64 t; cvta.to.shared.u64 t, %1; cvt.u32.u64 %0, t; }" : "=r"(a) : "l"(p));
    return a;
}
__device__ __forceinline__ void mbar_init(uint32_t a) {
    asm volatile("mbarrier.init.shared.b64 [%0], 1;" :: "r"(a) : "memory");
}
__device__ __forceinline__ void mbar_expect_tx(uint32_t a, uint32_t bytes) {
    asm volatile("mbarrier.arrive.expect_tx.shared.b64 _, [%0], %1;" :: "r"(a), "r"(bytes) : "memory");
}
__device__ __forceinline__ void mbar_wait(uint32_t mbar, int parity) {
    asm volatile(
        "{\n\t.reg .pred P;\n\t"
        "WL_%=:\n\t"
        "mbarrier.try_wait.parity.acquire.cta.shared::cta.b64 P, [%0], %1, 0x989680;\n\t"
        "@P bra.uni WD_%=;\n\t"
        "bra.uni WL_%=;\n\t"
        "WD_%=:\n\t}"
        :: "r"(mbar), "r"(parity) : "memory");
}
__device__ __forceinline__ void bulk_g2s(uint32_t dst, const void* src, uint32_t bytes, uint32_t mbar) {
    asm volatile(
        "cp.async.bulk.shared::cluster.global.mbarrier::complete_tx::bytes [%0], [%1], %2, [%3];"
        :: "r"(dst), "l"(src), "r"(bytes), "r"(mbar) : "memory");
}
#define FENCE_ASYNC() asm volatile("fence.proxy.async.shared::cta;" ::: "memory")

// ---------------------------------------------------------------------------
// Routing (int64/int32 safe) + flag clear for gemm2 handshake
// ---------------------------------------------------------------------------
__global__ void route_kernel(const void* __restrict__ pos) {
    __shared__ int cnt[NEXP], off[NEXP], cur[NEXP];
    __shared__ int s_not64;
    const int tid = threadIdx.x;
    if (tid < NEXP) { cnt[tid] = 0; cur[tid] = 0; }
    if (tid == 0) s_not64 = 0;
    if (tid < NTILES * 6) g_flag[tid] = 0;
    __syncthreads();
    const unsigned long long* pl = (const unsigned long long*)pos;
    for (int i = tid; i < T_TOK / 2; i += blockDim.x)
        if (pl[i] > 7ULL) s_not64 = 1;
    __syncthreads();
    const int is64 = !s_not64;
    const long long* p64 = (const long long*)pos;
    const int*       p32 = (const int*)pos;
    for (int t = tid; t < T_TOK; t += blockDim.x) {
        int e = is64 ? (int)p64[t] : p32[t];
        atomicAdd(&cnt[e], 1);
    }
    for (int i = tid; i < PADROWS; i += blockDim.x) g_perm[i] = -1;
    __syncthreads();
    if (tid == 0) {
        int o = 0;
        for (int e = 0; e < NEXP; e++) {
            off[e] = o;
            int nt = (cnt[e] + TM - 1) / TM;
            for (int k = 0; k < nt; k++) g_tile_expert[o / TM + k] = e;
            o += nt * TM;
        }
        for (int tl = o / TM; tl < NTILES; tl++) g_tile_expert[tl] = -1;
    }
    __syncthreads();
    for (int t = tid; t < T_TOK; t += blockDim.x) {
        int e = is64 ? (int)p64[t] : p32[t];
        int p = off[e] + atomicAdd(&cur[e], 1);
        g_perm[p] = t;
    }
}

// ---------------------------------------------------------------------------
// cvt: fp32 -> fp16 into tiled layouts
// ---------------------------------------------------------------------------
__device__ __forceinline__ uint4 cvt8(const float* src) {
    float4 v0 = *(const float4*)src;
    float4 v1 = *(const float4*)(src + 4);
    __half2 h0 = __floats2half2_rn(v0.x, v0.y), h1 = __floats2half2_rn(v0.z, v0.w);
    __half2 h2 = __floats2half2_rn(v1.x, v1.y), h3 = __floats2half2_rn(v1.z, v1.w);
    uint4 o;
    o.x = *(uint32_t*)&h0; o.y = *(uint32_t*)&h1;
    o.z = *(uint32_t*)&h2; o.w = *(uint32_t*)&h3;
    return o;
}

// y-half of the gate/up interleaved layout, 2 independent elements per thread
#define WGU_HTOT (NEXP * 16 * 12 * 128 * 9)
__global__ void cvt_wgu(const float* __restrict__ gw, const float* __restrict__ uw, int y0) {
    const int HALF = WGU_HTOT / 2;
    int i = blockIdx.x * 256 + threadIdx.x;
    if (i >= HALF) return;
#pragma unroll
    for (int rep = 0; rep < 2; rep++) {
        int idx = i + rep * HALF;
        int c8 = idx % 9; int t1 = idx / 9;
        int r  = t1 % 128; t1 /= 128;
        int kc = t1 % 12;  t1 /= 12;
        int y  = y0 + (t1 % 16);  int e = t1 / 16;
        uint4 o = make_uint4(0, 0, 0, 0);
        if (c8 < 8) {
            int q = r & 63;
            int wrow = y * 64 + (r >> 6) * 32 + (q & 31);
            const float* src = ((q < 32) ? gw : uw) + ((size_t)e * IDIM + wrow) * DDIM + kc * 64 + c8 * 8;
            o = cvt8(src);
        }
        size_t dst = ((((size_t)(e * 32 + y) * 12 + kc) * 128 + r) * 9 + c8) * 8;
        *(uint4*)(g_wgu + dst) = o;
    }
}

__global__ void cvt_wd(const float* __restrict__ dw) {
    const int TOT = NEXP * 6 * 32 * 128 * 9;
    int idx = blockIdx.x * 256 + threadIdx.x;
    if (idx >= TOT) return;
    int c8 = idx % 9; int t1 = idx / 9;
    int r  = t1 % 128; t1 /= 128;
    int kc = t1 % 32;  t1 /= 32;
    int y  = t1 % 6;   int e = t1 / 6;
    uint4 o = make_uint4(0, 0, 0, 0);
    if (c8 < 8) {
        const float* src = dw + ((size_t)e * DDIM + y * 128 + r) * IDIM + kc * 64 + c8 * 8;
        o = cvt8(src);
    }
    *(uint4*)(g_wdt + (size_t)idx * 8) = o;
}

__global__ void cvt_x(const float* __restrict__ x) {   // run AFTER route
    const int TOT = NTILES * 12 * 128 * 9;
    int idx = blockIdx.x * 256 + threadIdx.x;
    if (idx >= TOT) return;
    int c8 = idx % 9; int t1 = idx / 9;
    int r  = t1 % 128; t1 /= 128;
    int kc = t1 % 12;  int tile = t1 / 12;
    uint4 o = make_uint4(0, 0, 0, 0);
    int t = g_perm[tile * TM + r];
    if (c8 < 8 && t >= 0)
        o = cvt8(x + (size_t)t * DDIM + kc * 64 + c8 * 8);
    *(uint4*)(g_xt + (size_t)idx * 8) = o;
}

// ---------------------------------------------------------------------------
// GEMM1: 128x128 CTA tile (64 G cols + 64 U cols), 4 warps (2x2), warp 64x64.
// In-register silu(G)*U. 2-stage bulk pipeline, 3 CTA/SM.  (r9 exact)
// ---------------------------------------------------------------------------
__global__ __launch_bounds__(128, 3) __cluster_dims__(1, 1, 1) void gemm1_kernel() {
    const int tile = blockIdx.x;
    const int e = g_tile_expert[tile];
    if (e < 0) return;
    const int y = blockIdx.y;          // 64-col block (== gemm2 k-chunk index)

    extern __shared__ __align__(128) char sh[];
    __shared__ __align__(8) unsigned long long mbars[NSTAGE];
    const uint32_t sb = smem_u32(sh);
    const uint32_t mb0 = smem_u32(mbars);
    const int tid = threadIdx.x;

    if (tid == 0)
        for (int s = 0; s < NSTAGE; s++) mbar_init(mb0 + 8 * s);
    __syncthreads();

    const __half* Asrc = g_xt  + (size_t)tile * 12 * 128 * LDH;
    const __half* Bsrc = g_wgu + (size_t)((e * 32 + y) * 12) * 128 * LDH;

    const int NK = DDIM / KC;  // 12
    if (tid == 0) {
        FENCE_ASYNC();
#pragma unroll
        for (int s = 0; s < NSTAGE; s++) {
            mbar_expect_tx(mb0 + 8 * s, STAGE_BYTES);
            bulk_g2s(sb + s * STAGE_BYTES,              Asrc + (size_t)s * 128 * LDH, TILE_BYTES, mb0 + 8 * s);
            bulk_g2s(sb + s * STAGE_BYTES + TILE_BYTES, Bsrc + (size_t)s * 128 * LDH, TILE_BYTES, mb0 + 8 * s);
        }
    }

    const int wid = tid >> 5, wm = wid >> 1, wn = wid & 1;
    wmma::fragment<wmma::accumulator, 16, 16, 16, float> acc[4][4];
#pragma unroll
    for (int i = 0; i < 4; i++)
#pragma unroll
        for (int j = 0; j < 4; j++) wmma::fill_fragment(acc[i][j], 0.0f);

    for (int kc = 0; kc < NK; kc++) {
        const int s = kc & 1;
        mbar_wait(mb0 + 8 * s, (kc >> 1) & 1);
        const __half* A = (const __half*)(sh + s * STAGE_BYTES);
        const __half* B = (const __half*)(sh + s * STAGE_BYTES + TILE_BYTES);
#pragma unroll
        for (int ks = 0; ks < KC / 16; ks++) {
            wmma::fragment<wmma::matrix_a, 16, 16, 16, __half, wmma::row_major> fa[4];
            wmma::fragment<wmma::matrix_b, 16, 16, 16, __half, wmma::col_major> fb[4];
#pragma unroll
            for (int i = 0; i < 4; i++)
                wmma::load_matrix_sync(fa[i], A + (wm * 64 + i * 16) * LDH + ks * 16, LDH);
#pragma unroll
            for (int j = 0; j < 4; j++)
                wmma::load_matrix_sync(fb[j], B + (wn * 64 + j * 16) * LDH + ks * 16, LDH);
#pragma unroll
            for (int i = 0; i < 4; i++)
#pragma unroll
                for (int j = 0; j < 4; j++)
                    wmma::mma_sync(acc[i][j], fa[i], fb[j], acc[i][j]);
        }
        __syncthreads();
        int kn = kc + NSTAGE;
        if (kn < NK && tid == 0) {
            mbar_expect_tx(mb0 + 8 * s, STAGE_BYTES);
            bulk_g2s(sb + s * STAGE_BYTES,              Asrc + (size_t)kn * 128 * LDH, TILE_BYTES, mb0 + 8 * s);
            bulk_g2s(sb + s * STAGE_BYTES + TILE_BYTES, Bsrc + (size_t)kn * 128 * LDH, TILE_BYTES, mb0 + 8 * s);
        }
    }

    // In-register silu(G)*U, stage fp32 h (128 x 64, stride 68), write fp16 tile
    float* st = (float*)sh;   // 128*68*4 = 34816 B <= 73728
    __syncthreads();
#pragma unroll
    for (int i = 0; i < 4; i++)
#pragma unroll
        for (int jj = 0; jj < 2; jj++) {
#pragma unroll
            for (int el = 0; el < acc[i][jj].num_elements; el++) {
                float g = acc[i][jj].x[el];
                float u = acc[i][jj + 2].x[el];
                acc[i][jj].x[el] = (g / (1.0f + __expf(-g))) * u;
            }
            wmma::store_matrix_sync(st + (wm * 64 + i * 16) * LDST2 + wn * 32 + jj * 16,
                                    acc[i][jj], LDST2, wmma::mem_row_major);
        }
    __syncthreads();

    __half* hdst = g_ht + (size_t)(tile * 32 + y) * 128 * LDH;
#pragma unroll
    for (int j = 0; j < 32; j++) {               // 128 rows x 32 half2 cols
        int p = tid + 128 * j;
        int r = p >> 5, c2 = p & 31;
        float h0 = st[r * LDST2 + c2 * 2];
        float h1 = st[r * LDST2 + c2 * 2 + 1];
        __half2 hv = __floats2half2_rn(h0, h1);
        *(uint32_t*)(hdst + r * LDH + c2 * 2) = *(uint32_t*)&hv;
    }
}

// ---------------------------------------------------------------------------
// GEMM2: split-K (blockIdx.z). 128x128 CTA, 4 warps, 64x64.
// z=0 writes partial to g_gp + sets flag; z=1 polls flag (in epilogue, after
// its mainloop — all z=0 CTAs are bids 0-239, resident from wave 1, so no
// deadlock), adds partial, scatters to out.
// ---------------------------------------------------------------------------
__global__ __launch_bounds__(128, 3) __cluster_dims__(1, 1, 1) void gemm2_kernel(float* __restrict__ out) {
    const int tile = blockIdx.x;
    const int e = g_tile_expert[tile];
    if (e < 0) return;
    const int y = blockIdx.y;
    const int z = blockIdx.z;

    extern __shared__ __align__(128) char sh[];
    __shared__ __align__(8) unsigned long long mbars[NSTAGE];
    __shared__ int rowtok[128];
    const uint32_t sb = smem_u32(sh);
    const uint32_t mb0 = smem_u32(mbars);
    const int tid = threadIdx.x;

    if (tid == 0)
        for (int s = 0; s < NSTAGE; s++) mbar_init(mb0 + 8 * s);
    if (tid < 128) rowtok[tid] = g_perm[tile * TM + tid];
    __syncthreads();

    const __half* Asrc = g_ht  + (size_t)(tile * 32 + z * 16) * 128 * LDH;
    const __half* Bsrc = g_wdt + (size_t)((e * 6 + y) * 32 + z * 16) * 128 * LDH;

    const int NK = 16;
    if (tid == 0) {
        FENCE_ASYNC();
#pragma unroll
        for (int s = 0; s < NSTAGE; s++) {
            mbar_expect_tx(mb0 + 8 * s, STAGE_BYTES);
            bulk_g2s(sb + s * STAGE_BYTES,              Asrc + (size_t)s * 128 * LDH, TILE_BYTES, mb0 + 8 * s);
            bulk_g2s(sb + s * STAGE_BYTES + TILE_BYTES, Bsrc + (size_t)s * 128 * LDH, TILE_BYTES, mb0 + 8 * s);
        }
    }

    const int wid = tid >> 5, wm = wid >> 1, wn = wid & 1;
    wmma::fragment<wmma::accumulator, 16, 16, 16, float> acc[4][4];
#pragma unroll
    for (int i = 0; i < 4; i++)
#pragma unroll
        for (int j = 0; j < 4; j++) wmma::fill_fragment(acc[i][j], 0.0f);

    for (int kc = 0; kc < NK; kc++) {
        const int s = kc & 1;
        mbar_wait(mb0 + 8 * s, (kc >> 1) & 1);
        const __half* A = (const __half*)(sh + s * STAGE_BYTES);
        const __half* B = (const __half*)(sh + s * STAGE_BYTES + TILE_BYTES);
#pragma unroll
        for (int ks = 0; ks < KC / 16; ks++) {
            wmma::fragment<wmma::matrix_a, 16, 16, 16, __half, wmma::row_major> fa[4];
            wmma::fragment<wmma::matrix_b, 16, 16, 16, __half, wmma::col_major> fb[4];
#pragma unroll
            for (int i = 0; i < 4; i++)
                wmma::load_matrix_sync(fa[i], A + (wm * 64 + i * 16) * LDH + ks * 16, LDH);
#pragma unroll
            for (int j = 0; j < 4; j++)
                wmma::load_matrix_sync(fb[j], B + (wn * 64 + j * 16) * LDH + ks * 16, LDH);
#pragma unroll
            for (int i = 0; i < 4; i++)
#pragma unroll
                for (int j = 0; j < 4; j++)
                    wmma::mma_sync(acc[i][j], fa[i], fb[j], acc[i][j]);
        }
        __syncthreads();
        int kn = kc + NSTAGE;
        if (kn < NK && tid == 0) {
            mbar_expect_tx(mb0 + 8 * s, STAGE_BYTES);
            bulk_g2s(sb + s * STAGE_BYTES,              Asrc + (size_t)kn * 128 * LDH, TILE_BYTES, mb0 + 8 * s);
            bulk_g2s(sb + s * STAGE_BYTES + TILE_BYTES, Bsrc + (size_t)kn * 128 * LDH, TILE_BYTES, mb0 + 8 * s);
        }
    }

    // Stage fp32 (128 x 132).
    float* st = (float*)sh;
    __syncthreads();
#pragma unroll
    for (int i = 0; i < 4; i++)
#pragma unroll
        for (int j = 0; j < 4; j++)
            wmma::store_matrix_sync(st + (wm * 64 + i * 16) * LDST + wn * 64 + j * 16,
                                    acc[i][j], LDST, wmma::mem_row_major);
    __syncthreads();

    if (z == 0) {
        // write partial (permuted order), release flag
        float* dst = g_gp + ((size_t)tile * 128) * DDIM + y * 128;
#pragma unroll
        for (int j = 0; j < 32; j++) {
            int p = tid + 128 * j;
            int r = p >> 5, c4 = (p & 31) * 4;
            *(float4*)(dst + (size_t)r * DDIM + c4) = *(float4*)&st[r * LDST + c4];
        }
        __threadfence();
        __syncthreads();
        if (tid == 0) atomicExch(&g_flag[tile * 6 + y], 1);
    } else {
        // acquire partial, add, scatter to out
        if (tid == 0)
            while (atomicAdd(&g_flag[tile * 6 + y], 0) == 0) __nanosleep(100);
        __syncthreads();
        const float* src = g_gp + ((size_t)tile * 128) * DDIM + y * 128;
#pragma unroll
        for (int j = 0; j < 32; j++) {
            int p = tid + 128 * j;
            int r = p >> 5, c4 = (p & 31) * 4;
            int t = rowtok[r];
            if (t >= 0) {
                float4 a = __ldcg((const float4*)(src + (size_t)r * DDIM + c4));
                float4 b = *(float4*)&st[r * LDST + c4];
                float4 o = make_float4(a.x + b.x, a.y + b.y, a.z + b.z, a.w + b.w);
                *(float4*)(out + (size_t)t * DDIM + y * 128 + c4) = o;
            }
        }
    }
}

// ---------------------------------------------------------------------------
extern "C" void kernel_launch(void* const* d_in, const int* in_sizes, int n_in,
                              void* d_out, int out_size) {
    const float* x   = (const float*)d_in[0];
    const void*  pos = d_in[1];
    // d_in[2] = behavior_index: unused
    const float* gw  = (const float*)d_in[3];
    const float* uw  = (const float*)d_in[4];
    const float* dw  = (const float*)d_in[5];
    float* out = (float*)d_out;

    static cudaStream_t s2 = nullptr, s3 = nullptr;
    static cudaEvent_t eFork = nullptr, eWa = nullptr, eWb = nullptr, eWd = nullptr;
    if (!s2) {
        cudaStreamCreateWithFlags(&s2, cudaStreamNonBlocking);
        cudaStreamCreateWithFlags(&s3, cudaStreamNonBlocking);
        cudaEventCreateWithFlags(&eFork, cudaEventDisableTiming);
        cudaEventCreateWithFlags(&eWa, cudaEventDisableTiming);
        cudaEventCreateWithFlags(&eWb, cudaEventDisableTiming);
        cudaEventCreateWithFlags(&eWd, cudaEventDisableTiming);
        cudaFuncSetAttribute(gemm1_kernel, cudaFuncAttributeMaxDynamicSharedMemorySize, GSMEM);
        cudaFuncSetAttribute(gemm2_kernel, cudaFuncAttributeMaxDynamicSharedMemorySize, GSMEM);
    }

    const int WGU_BLOCKS = (WGU_HTOT / 2 + 255) / 256;

    // Fork: both weight-conversion streams start immediately.
    cudaEventRecord(eFork, 0);
    cudaStreamWaitEvent(s2, eFork, 0);
    cudaStreamWaitEvent(s3, eFork, 0);

    // s2: gate/up conversion, y 0-15
    cvt_wgu<<<WGU_BLOCKS, 256, 0, s2>>>(gw, uw, 0);
    cudaEventRecord(eWa, s2);

    // s3: gate/up conversion y 16-31, then down-proj conversion
    cvt_wgu<<<WGU_BLOCKS, 256, 0, s3>>>(gw, uw, 16);
    cudaEventRecord(eWb, s3);
    cvt_wd<<<(NEXP * 6 * 32 * 128 * 9 + 255) / 256, 256, 0, s3>>>(dw);
    cudaEventRecord(eWd, s3);

    // main: routing (also clears flags) + x conversion
    route_kernel<<<1, 256>>>(pos);
    cvt_x<<<(NTILES * 12 * 128 * 9 + 255) / 256, 256>>>(x);

    // gemm1 (full grid): needs route+cvt_x (program order) + both wgu halves
    cudaStreamWaitEvent(0, eWa, 0);
    cudaStreamWaitEvent(0, eWb, 0);
    gemm1_kernel<<<dim3(NTILES, 32), 128, GSMEM>>>();

    // gemm2 (split-K fused combine): needs gemm1 (program order) + cvt_wd
    cudaStreamWaitEvent(0, eWd, 0);
    gemm2_kernel<<<dim3(NTILES, 6, 2), 128, GSMEM>>>(out);
}

// round 14
// speedup vs baseline: 1.0625x; 1.0625x over previous
#include <cuda_runtime.h>
#include <cuda_fp16.h>
#include <cstdint>

#define T_TOK 4096
#define DDIM  768
#define IDIM  2048
#define NEXP  8
#define TM    128
#define NTILES 40
#define PADROWS (NTILES*TM)
#define LDST  132            // gemm2 fp32 staging stride: %4==0, row %16B==0
#define LDST2 68             // gemm1 fp32 staging stride (64 cols)
#define TILE_BYTES 16384     // 128 rows x 64 halves, SW128-swizzled, unpadded
#define TILE_H     8192      // halves per tile
#define STAGE_BYTES (2 * TILE_BYTES)     // A + B: 32768
#define NSTAGE 2
#define G1SMEM (NSTAGE * STAGE_BYTES)    // 65536 -> 3 CTA/SM
#define G2SMEM 67584                     // stages 65536 + gemm2 staging needs 128*132*4

// ---------------- device-global scratch (swizzled tiled layouts) ------------
__device__ int    g_perm[PADROWS];
__device__ int    g_tile_expert[NTILES];
// [e][y:32][kc:12] tiles; rows interleaved [G0-31|U0-31|G32-63|U32-63]
__device__ __half g_wgu[(size_t)NEXP * 32 * 12 * TILE_H];
// [e][y:6][kc:32] tiles
__device__ __half g_wdt[(size_t)NEXP * 6 * 32 * TILE_H];
// [tile:40][kc:12] tiles
__device__ __half g_xt [(size_t)NTILES * 12 * TILE_H];
// [tile:40][kc:32] tiles
__device__ __half g_ht [(size_t)NTILES * 32 * TILE_H];
// split-K partials, permuted row order: [z:2][PADROWS][768]
__device__ float  g_gp [(size_t)2 * PADROWS * DDIM];

// ---------------- PTX helpers -----------------------------------------------
__device__ __forceinline__ uint32_t smem_u32(const void* p) {
    uint32_t a;
    asm("{ .reg .u64 t; cvta.to.shared.u64 t, %1; cvt.u32.u64 %0, t; }" : "=r"(a) : "l"(p));
    return a;
}
__device__ __forceinline__ void mbar_init(uint32_t a) {
    asm volatile("mbarrier.init.shared.b64 [%0], 1;" :: "r"(a) : "memory");
}
__device__ __forceinline__ void mbar_expect_tx(uint32_t a, uint32_t bytes) {
    asm volatile("mbarrier.arrive.expect_tx.shared.b64 _, [%0], %1;" :: "r"(a), "r"(bytes) : "memory");
}
__device__ __forceinline__ void mbar_wait(uint32_t mbar, int parity) {
    asm volatile(
        "{\n\t.reg .pred P;\n\t"
        "WL_%=:\n\t"
        "mbarrier.try_wait.parity.acquire.cta.shared::cta.b64 P, [%0], %1, 0x989680;\n\t"
        "@P bra.uni WD_%=;\n\t"
        "bra.uni WL_%=;\n\t"
        "WD_%=:\n\t}"
        :: "r"(mbar), "r"(parity) : "memory");
}
__device__ __forceinline__ void bulk_g2s(uint32_t dst, const void* src, uint32_t bytes, uint32_t mbar) {
    asm volatile(
        "cp.async.bulk.shared::cluster.global.mbarrier::complete_tx::bytes [%0], [%1], %2, [%3];"
        :: "r"(dst), "l"(src), "r"(bytes), "r"(mbar) : "memory");
}
#define FENCE_ASYNC() asm volatile("fence.proxy.async.shared::cta;" ::: "memory")

__device__ __forceinline__ void ldsm4(uint32_t& r0, uint32_t& r1, uint32_t& r2, uint32_t& r3,
                                      uint32_t addr) {
    asm volatile("ldmatrix.sync.aligned.m8n8.x4.shared.b16 {%0,%1,%2,%3}, [%4];"
                 : "=r"(r0), "=r"(r1), "=r"(r2), "=r"(r3) : "r"(addr));
}
__device__ __forceinline__ void mma16816(float* d, const uint32_t* a, uint32_t b0, uint32_t b1) {
    asm volatile(
        "mma.sync.aligned.m16n8k16.row.col.f32.f16.f16.f32 "
        "{%0,%1,%2,%3}, {%4,%5,%6,%7}, {%8,%9}, {%0,%1,%2,%3};"
        : "+f"(d[0]), "+f"(d[1]), "+f"(d[2]), "+f"(d[3])
        : "r"(a[0]), "r"(a[1]), "r"(a[2]), "r"(a[3]), "r"(b0), "r"(b1));
}

// ---------------------------------------------------------------------------
// Routing (int64/int32 safe) — r9 exact
// ---------------------------------------------------------------------------
__global__ void route_kernel(const void* __restrict__ pos) {
    __shared__ int cnt[NEXP], off[NEXP], cur[NEXP];
    __shared__ int s_not64;
    const int tid = threadIdx.x;
    if (tid < NEXP) { cnt[tid] = 0; cur[tid] = 0; }
    if (tid == 0) s_not64 = 0;
    __syncthreads();
    const unsigned long long* pl = (const unsigned long long*)pos;
    for (int i = tid; i < T_TOK / 2; i += blockDim.x)
        if (pl[i] > 7ULL) s_not64 = 1;
    __syncthreads();
    const int is64 = !s_not64;
    const long long* p64 = (const long long*)pos;
    const int*       p32 = (const int*)pos;
    for (int t = tid; t < T_TOK; t += blockDim.x) {
        int e = is64 ? (int)p64[t] : p32[t];
        atomicAdd(&cnt[e], 1);
    }
    for (int i = tid; i < PADROWS; i += blockDim.x) g_perm[i] = -1;
    __syncthreads();
    if (tid == 0) {
        int o = 0;
        for (int e = 0; e < NEXP; e++) {
            off[e] = o;
            int nt = (cnt[e] + TM - 1) / TM;
            for (int k = 0; k < nt; k++) g_tile_expert[o / TM + k] = e;
            o += nt * TM;
        }
        for (int tl = o / TM; tl < NTILES; tl++) g_tile_expert[tl] = -1;
    }
    __syncthreads();
    for (int t = tid; t < T_TOK; t += blockDim.x) {
        int e = is64 ? (int)p64[t] : p32[t];
        int p = off[e] + atomicAdd(&cur[e], 1);
        g_perm[p] = t;
    }
}

// ---------------------------------------------------------------------------
// cvt: fp32 -> fp16 into SWIZZLED unpadded tiles.
// Within-tile half offset for (r, c8 16B-chunk): r*64 + ((c8 ^ (r&7)) << 3)
// ---------------------------------------------------------------------------
__device__ __forceinline__ uint4 cvt8(const float* src) {
    float4 v0 = *(const float4*)src;
    float4 v1 = *(const float4*)(src + 4);
    __half2 h0 = __floats2half2_rn(v0.x, v0.y), h1 = __floats2half2_rn(v0.z, v0.w);
    __half2 h2 = __floats2half2_rn(v1.x, v1.y), h3 = __floats2half2_rn(v1.z, v1.w);
    uint4 o;
    o.x = *(uint32_t*)&h0; o.y = *(uint32_t*)&h1;
    o.z = *(uint32_t*)&h2; o.w = *(uint32_t*)&h3;
    return o;
}

#define WGU_HTOT (NEXP * 16 * 12 * 128 * 8)
__global__ void cvt_wgu(const float* __restrict__ gw, const float* __restrict__ uw, int y0) {
    int idx = blockIdx.x * 256 + threadIdx.x;
    if (idx >= WGU_HTOT) return;
    int c8 = idx & 7; int t1 = idx >> 3;
    int r  = t1 % 128; t1 /= 128;
    int kc = t1 % 12;  t1 /= 12;
    int y  = y0 + (t1 % 16);  int e = t1 / 16;
    int q = r & 63;
    int wrow = y * 64 + (r >> 6) * 32 + (q & 31);
    const float* src = ((q < 32) ? gw : uw) + ((size_t)e * IDIM + wrow) * DDIM + kc * 64 + c8 * 8;
    uint4 o = cvt8(src);
    size_t dst = ((size_t)((e * 32 + y) * 12 + kc)) * TILE_H + r * 64 + ((c8 ^ (r & 7)) << 3);
    *(uint4*)(g_wgu + dst) = o;
}

__global__ void cvt_wd(const float* __restrict__ dw) {
    const int TOT = NEXP * 6 * 32 * 128 * 8;
    int idx = blockIdx.x * 256 + threadIdx.x;
    if (idx >= TOT) return;
    int c8 = idx & 7; int t1 = idx >> 3;
    int r  = t1 % 128; t1 /= 128;
    int kc = t1 % 32;  t1 /= 32;
    int y  = t1 % 6;   int e = t1 / 6;
    const float* src = dw + ((size_t)e * DDIM + y * 128 + r) * IDIM + kc * 64 + c8 * 8;
    uint4 o = cvt8(src);
    size_t dst = ((size_t)((e * 6 + y) * 32 + kc)) * TILE_H + r * 64 + ((c8 ^ (r & 7)) << 3);
    *(uint4*)(g_wdt + dst) = o;
}

__global__ void cvt_x(const float* __restrict__ x) {   // run AFTER route
    const int TOT = NTILES * 12 * 128 * 8;
    int idx = blockIdx.x * 256 + threadIdx.x;
    if (idx >= TOT) return;
    int c8 = idx & 7; int t1 = idx >> 3;
    int r  = t1 % 128; t1 /= 128;
    int kc = t1 % 12;  int tile = t1 / 12;
    uint4 o = make_uint4(0, 0, 0, 0);
    int t = g_perm[tile * TM + r];
    if (t >= 0)
        o = cvt8(x + (size_t)t * DDIM + kc * 64 + c8 * 8);
    size_t dst = ((size_t)(tile * 12 + kc)) * TILE_H + r * 64 + ((c8 ^ (r & 7)) << 3);
    *(uint4*)(g_xt + dst) = o;
}

// ---------------------------------------------------------------------------
// GEMM mainloop core: warp tile 64x64, ldmatrix+mma.sync on swizzled tiles.
// acc layout: acc[((i*4+j)*2+sub)*4 + k], i=A 16-row blk, j=B 16-row blk.
// ---------------------------------------------------------------------------
struct LaneCtx {
    uint32_t aRow[4], bRow[4], lx;
    uint32_t selA, selB;
    int wm, wn, l;
};
__device__ __forceinline__ LaneCtx make_ctx(int tid) {
    LaneCtx c;
    c.l = tid & 31;
    int wid = tid >> 5;
    c.wm = wid >> 1; c.wn = wid & 1;
    c.lx = c.l & 7;
#pragma unroll
    for (int i = 0; i < 4; i++)
        c.aRow[i] = (c.wm * 64 + i * 16 + (c.l & 15)) * 128;
    int nB = (c.l & 7) + ((c.l & 16) >> 1);
#pragma unroll
    for (int j = 0; j < 4; j++)
        c.bRow[j] = (c.wn * 64 + j * 16 + nB) * 128;
    c.selA = c.l >> 4;
    c.selB = (c.l >> 3) & 1;
    return c;
}
__device__ __forceinline__ void chunk_mma(const LaneCtx& c, uint32_t Ab, uint32_t Bb, float* acc) {
#pragma unroll
    for (int ks = 0; ks < 4; ks++) {
        uint32_t cA = ((((uint32_t)(ks << 1) | c.selA) ^ c.lx) << 4);
        uint32_t cB = ((((uint32_t)(ks << 1) | c.selB) ^ c.lx) << 4);
        uint32_t a[4][4];
#pragma unroll
        for (int i = 0; i < 4; i++)
            ldsm4(a[i][0], a[i][1], a[i][2], a[i][3], Ab + c.aRow[i] + cA);
#pragma unroll
        for (int j = 0; j < 4; j++) {
            uint32_t b[4];
            ldsm4(b[0], b[1], b[2], b[3], Bb + c.bRow[j] + cB);
#pragma unroll
            for (int i = 0; i < 4; i++) {
                mma16816(acc + ((i * 4 + j) * 2 + 0) * 4, a[i], b[0], b[1]);
                mma16816(acc + ((i * 4 + j) * 2 + 1) * 4, a[i], b[2], b[3]);
            }
        }
    }
}

// ---------------------------------------------------------------------------
// GEMM1: 128x128 CTA tile (64 G + 64 U cols), 4 warps, warp 64x64, 3 CTA/SM.
// ---------------------------------------------------------------------------
__global__ __launch_bounds__(128, 3) void gemm1_kernel() {
    const int tile = blockIdx.x;
    const int e = g_tile_expert[tile];
    if (e < 0) return;
    const int y = blockIdx.y;

    extern __shared__ __align__(128) char sh[];
    __shared__ __align__(8) unsigned long long mbars[NSTAGE];
    const uint32_t sb = smem_u32(sh);
    const uint32_t mb0 = smem_u32(mbars);
    const int tid = threadIdx.x;

    if (tid == 0)
        for (int s = 0; s < NSTAGE; s++) mbar_init(mb0 + 8 * s);
    __syncthreads();

    const __half* Asrc = g_xt  + (size_t)tile * 12 * TILE_H;
    const __half* Bsrc = g_wgu + (size_t)((e * 32 + y) * 12) * TILE_H;

    const int NK = 12;
    if (tid == 0) {
        FENCE_ASYNC();
#pragma unroll
        for (int s = 0; s < NSTAGE; s++) {
            mbar_expect_tx(mb0 + 8 * s, STAGE_BYTES);
            bulk_g2s(sb + s * STAGE_BYTES,              Asrc + (size_t)s * TILE_H, TILE_BYTES, mb0 + 8 * s);
            bulk_g2s(sb + s * STAGE_BYTES + TILE_BYTES, Bsrc + (size_t)s * TILE_H, TILE_BYTES, mb0 + 8 * s);
        }
    }

    LaneCtx c = make_ctx(tid);
    float acc[128];
#pragma unroll
    for (int k = 0; k < 128; k++) acc[k] = 0.0f;

    for (int kc = 0; kc < NK; kc++) {
        const int s = kc & 1;
        mbar_wait(mb0 + 8 * s, (kc >> 1) & 1);
        chunk_mma(c, sb + s * STAGE_BYTES, sb + s * STAGE_BYTES + TILE_BYTES, acc);
        __syncthreads();
        int kn = kc + NSTAGE;
        if (kn < NK && tid == 0) {
            mbar_expect_tx(mb0 + 8 * s, STAGE_BYTES);
            bulk_g2s(sb + s * STAGE_BYTES,              Asrc + (size_t)kn * TILE_H, TILE_BYTES, mb0 + 8 * s);
            bulk_g2s(sb + s * STAGE_BYTES + TILE_BYTES, Bsrc + (size_t)kn * TILE_H, TILE_BYTES, mb0 + 8 * s);
        }
    }

    // In-register silu(G)*U -> fp32 staging (128 x 64, stride 68)
    float* st = (float*)sh;
    __syncthreads();
    const int r0l = c.l >> 2, c0l = (c.l & 3) * 2;
#pragma unroll
    for (int i = 0; i < 4; i++)
#pragma unroll
        for (int jj = 0; jj < 2; jj++)
#pragma unroll
            for (int sub = 0; sub < 2; sub++) {
                float* G = acc + ((i * 4 + jj) * 2 + sub) * 4;
                float* U = acc + ((i * 4 + jj + 2) * 2 + sub) * 4;
                float h0 = (G[0] / (1.0f + __expf(-G[0]))) * U[0];
                float h1 = (G[1] / (1.0f + __expf(-G[1]))) * U[1];
                float h2 = (G[2] / (1.0f + __expf(-G[2]))) * U[2];
                float h3 = (G[3] / (1.0f + __expf(-G[3]))) * U[3];
                int R = c.wm * 64 + i * 16 + r0l;
                int gc = c.wn * 32 + jj * 16 + sub * 8 + c0l;
                *(float2*)&st[R * LDST2 + gc]       = make_float2(h0, h1);
                *(float2*)&st[(R + 8) * LDST2 + gc] = make_float2(h2, h3);
            }
    __syncthreads();

    // write fp16 swizzled h tile
    char* hdst = (char*)g_ht + (size_t)(tile * 32 + y) * TILE_BYTES;
#pragma unroll
    for (int j = 0; j < 32; j++) {               // 128 rows x 32 half2 cols
        int p = tid + 128 * j;
        int r = p >> 5, c2 = p & 31;
        float h0 = st[r * LDST2 + c2 * 2];
        float h1 = st[r * LDST2 + c2 * 2 + 1];
        __half2 hv = __floats2half2_rn(h0, h1);
        uint32_t phys = r * 128 + ((((uint32_t)(c2 >> 2)) ^ (r & 7)) << 4) + (c2 & 3) * 4;
        *(uint32_t*)(hdst + phys) = *(uint32_t*)&hv;
    }
}

// ---------------------------------------------------------------------------
// GEMM2: split-K (blockIdx.z). 128x128 CTA, 4 warps, warp 64x64.
// ---------------------------------------------------------------------------
__global__ __launch_bounds__(128, 3) void gemm2_kernel() {
    const int tile = blockIdx.x;
    const int e = g_tile_expert[tile];
    if (e < 0) return;
    const int y = blockIdx.y;
    const int z = blockIdx.z;

    extern __shared__ __align__(128) char sh[];
    __shared__ __align__(8) unsigned long long mbars[NSTAGE];
    const uint32_t sb = smem_u32(sh);
    const uint32_t mb0 = smem_u32(mbars);
    const int tid = threadIdx.x;

    if (tid == 0)
        for (int s = 0; s < NSTAGE; s++) mbar_init(mb0 + 8 * s);
    __syncthreads();

    const __half* Asrc = g_ht  + (size_t)(tile * 32 + z * 16) * TILE_H;
    const __half* Bsrc = g_wdt + (size_t)((e * 6 + y) * 32 + z * 16) * TILE_H;

    const int NK = 16;
    if (tid == 0) {
        FENCE_ASYNC();
#pragma unroll
        for (int s = 0; s < NSTAGE; s++) {
            mbar_expect_tx(mb0 + 8 * s, STAGE_BYTES);
            bulk_g2s(sb + s * STAGE_BYTES,              Asrc + (size_t)s * TILE_H, TILE_BYTES, mb0 + 8 * s);
            bulk_g2s(sb + s * STAGE_BYTES + TILE_BYTES, Bsrc + (size_t)s * TILE_H, TILE_BYTES, mb0 + 8 * s);
        }
    }

    LaneCtx c = make_ctx(tid);
    float acc[128];
#pragma unroll
    for (int k = 0; k < 128; k++) acc[k] = 0.0f;

    for (int kc = 0; kc < NK; kc++) {
        const int s = kc & 1;
        mbar_wait(mb0 + 8 * s, (kc >> 1) & 1);
        chunk_mma(c, sb + s * STAGE_BYTES, sb + s * STAGE_BYTES + TILE_BYTES, acc);
        __syncthreads();
        int kn = kc + NSTAGE;
        if (kn < NK && tid == 0) {
            mbar_expect_tx(mb0 + 8 * s, STAGE_BYTES);
            bulk_g2s(sb + s * STAGE_BYTES,              Asrc + (size_t)kn * TILE_H, TILE_BYTES, mb0 + 8 * s);
            bulk_g2s(sb + s * STAGE_BYTES + TILE_BYTES, Bsrc + (size_t)kn * TILE_H, TILE_BYTES, mb0 + 8 * s);
        }
    }

    // Stage fp32 (128 x 132), write partial (permuted order).
    float* st = (float*)sh;
    __syncthreads();
    const int r0l = c.l >> 2, c0l = (c.l & 3) * 2;
#pragma unroll
    for (int i = 0; i < 4; i++)
#pragma unroll
        for (int j = 0; j < 4; j++)
#pragma unroll
            for (int sub = 0; sub < 2; sub++) {
                float* D = acc + ((i * 4 + j) * 2 + sub) * 4;
                int R = c.wm * 64 + i * 16 + r0l;
                int cc = c.wn * 64 + j * 16 + sub * 8 + c0l;
                *(float2*)&st[R * LDST + cc]       = make_float2(D[0], D[1]);
                *(float2*)&st[(R + 8) * LDST + cc] = make_float2(D[2], D[3]);
            }
    __syncthreads();

    float* dst = g_gp + ((size_t)z * PADROWS + tile * 128) * DDIM + y * 128;
#pragma unroll
    for (int j = 0; j < 32; j++) {               // 128 rows x 32 float4 cols
        int p = tid + 128 * j;
        int r = p >> 5, c4 = (p & 31) * 4;
        *(float4*)(dst + (size_t)r * DDIM + c4) = *(float4*)&st[r * LDST + c4];
    }
}

// ---------------------------------------------------------------------------
// add partials + scatter to output
// ---------------------------------------------------------------------------
__global__ void add_kernel(float* __restrict__ out) {
    int idx = blockIdx.x * 256 + threadIdx.x;
    if (idx >= PADROWS * (DDIM / 4)) return;
    int p = idx / (DDIM / 4), c4 = (idx % (DDIM / 4)) * 4;
    int t = g_perm[p];
    if (t < 0) return;
    const float* a = g_gp + (size_t)p * DDIM + c4;
    const float* b = g_gp + (size_t)(PADROWS + p) * DDIM + c4;
    float4 va = *(const float4*)a, vb = *(const float4*)b;
    float4 o = make_float4(va.x + vb.x, va.y + vb.y, va.z + vb.z, va.w + vb.w);
    *(float4*)(out + (size_t)t * DDIM + c4) = o;
}

// ---------------------------------------------------------------------------
extern "C" void kernel_launch(void* const* d_in, const int* in_sizes, int n_in,
                              void* d_out, int out_size) {
    const float* x   = (const float*)d_in[0];
    const void*  pos = d_in[1];
    // d_in[2] = behavior_index: unused
    const float* gw  = (const float*)d_in[3];
    const float* uw  = (const float*)d_in[4];
    const float* dw  = (const float*)d_in[5];
    float* out = (float*)d_out;

    static cudaStream_t s2 = nullptr, s3 = nullptr;
    static cudaEvent_t eFork = nullptr, eWa = nullptr, eWb = nullptr, eWd = nullptr;
    if (!s2) {
        cudaStreamCreateWithFlags(&s2, cudaStreamNonBlocking);
        cudaStreamCreateWithFlags(&s3, cudaStreamNonBlocking);
        cudaEventCreateWithFlags(&eFork, cudaEventDisableTiming);
        cudaEventCreateWithFlags(&eWa, cudaEventDisableTiming);
        cudaEventCreateWithFlags(&eWb, cudaEventDisableTiming);
        cudaEventCreateWithFlags(&eWd, cudaEventDisableTiming);
        cudaFuncSetAttribute(gemm1_kernel, cudaFuncAttributeMaxDynamicSharedMemorySize, G1SMEM);
        cudaFuncSetAttribute(gemm2_kernel, cudaFuncAttributeMaxDynamicSharedMemorySize, G2SMEM);
    }

    const int WGU_BLOCKS = (WGU_HTOT + 255) / 256;

    // Fork: both weight-conversion streams start immediately.
    cudaEventRecord(eFork, 0);
    cudaStreamWaitEvent(s2, eFork, 0);
    cudaStreamWaitEvent(s3, eFork, 0);

    // s2: gate/up conversion, y 0-15
    cvt_wgu<<<WGU_BLOCKS, 256, 0, s2>>>(gw, uw, 0);
    cudaEventRecord(eWa, s2);

    // s3: gate/up conversion y 16-31, then down-proj conversion
    cvt_wgu<<<WGU_BLOCKS, 256, 0, s3>>>(gw, uw, 16);
    cudaEventRecord(eWb, s3);
    cvt_wd<<<(NEXP * 6 * 32 * 128 * 8 + 255) / 256, 256, 0, s3>>>(dw);
    cudaEventRecord(eWd, s3);

    // main: routing + x conversion (concurrent with weight conversions)
    route_kernel<<<1, 256>>>(pos);
    cvt_x<<<(NTILES * 12 * 128 * 8 + 255) / 256, 256>>>(x);

    // gemm1: needs route+cvt_x (program order) + both wgu halves
    cudaStreamWaitEvent(0, eWa, 0);
    cudaStreamWaitEvent(0, eWb, 0);
    gemm1_kernel<<<dim3(NTILES, 32), 128, G1SMEM>>>();

    // gemm2: needs gemm1 (program order) + cvt_wd (hidden under gemm1)
    cudaStreamWaitEvent(0, eWd, 0);
    gemm2_kernel<<<dim3(NTILES, 6, 2), 128, G2SMEM>>>();
    add_kernel<<<(PADROWS * (DDIM / 4) + 255) / 256, 256>>>(out);
}